// round 11
// baseline (speedup 1.0000x reference)
#include <cuda_runtime.h>
#include <cuda_fp16.h>
#include <cstdint>

// out[b,t] = cumsum_t( relu(x @ Wh^T + bh) ) + (x @ Wb^T + bb)
//   x [16384,1024] f32, Wh [512,1024] f32, bh[512], Wb[1,1024], bb[1]
//
// fp16 mma.sync m16n8k16. BOTH operands pre-converted to fp16 fragment-order
// gmem streams (prep_wh / prep_x prepasses; prep_x also computes the exact
// fp32 base GEMV g_base = x@Wb). Main kernel: CTA = 32 rows x 512 cols,
// 256 threads (8 warps, warp tile 32x64), 2 CTAs/SM, NO smem / NO barriers
// in the mainloop -- pure LDG.128 + MMA streams per warp, consume-then-
// reload pipelined. In-register scan epilogue (one barrier for the
// cross-warp segment prefix).

#define DDIM   1024
#define TDIM   512
#define BROWS  16384
#define MTILE  32
#define NCH    32
#define NTHREADS 256

__device__ __half g_whs[TDIM * DDIM];   // B: [chunk][jg][lane][8 halfs]
__device__ __half g_xh[BROWS * DDIM];   // A: [tile][chunk][(i,G)][lane][8 halfs]
__device__ float  g_base[BROWS];        // x @ Wb (fp32 exact)

__device__ __forceinline__ void mma_f16(float* c, uint32_t a0, uint32_t a1,
                                        uint32_t a2, uint32_t a3,
                                        uint32_t b0, uint32_t b1) {
    asm volatile(
        "mma.sync.aligned.m16n8k16.row.col.f32.f16.f16.f32 "
        "{%0,%1,%2,%3}, {%4,%5,%6,%7}, {%8,%9}, {%0,%1,%2,%3};"
        : "+f"(c[0]), "+f"(c[1]), "+f"(c[2]), "+f"(c[3])
        : "r"(a0), "r"(a1), "r"(a2), "r"(a3), "r"(b0), "r"(b1));
}

// prepass B: Wh -> fp16 fragment order (as R8-R10):
//   (t,k): c=k>>5, G=(k>>4)&1, u=(k>>3)&1, lk=(k&7)>>1, w=k&1
//   jg=t>>3, l4=t&7, lane=4*l4+lk, h=4*G+2*u+w
__global__ void __launch_bounds__(256) prep_wh_kernel(const float* __restrict__ Wh) {
    const int t  = blockIdx.x;
    const int k4 = threadIdx.x * 4;
    float4 v = *(const float4*)(Wh + (size_t)t * DDIM + k4);
    const int jg = t >> 3, l4 = t & 7;
    #pragma unroll
    for (int e = 0; e < 4; e++) {
        int k = k4 + e;
        int c = k >> 5, G = (k >> 4) & 1, u = (k >> 3) & 1;
        int lk = (k & 7) >> 1, w = k & 1;
        g_whs[(size_t)c * 16384 + jg * 256 + (4 * l4 + lk) * 8 + 4 * G + 2 * u + w] =
            __float2half_rn(((const float*)&v)[e]);
    }
}

// prepass A: x -> fp16 A-fragment order + exact fp32 base GEMV.
//   row: tile=row>>5, i=(row>>4)&1, rh=(row>>3)&1, l4r=row&7
//   k: c=k>>5, k5=k&31, G=(k5>>4)&1, u=(k5>>3)&1, lk=(k5&7)>>1, w=k5&1
//   idx = (tile*32+c)*1024 + (i*2+G)*256 + (4*l4r+lk)*8 + (4*u+2*rh+w)
__global__ void __launch_bounds__(256) prep_x_kernel(const float* __restrict__ x,
                                                     const float* __restrict__ Wb) {
    const int row = blockIdx.x;
    const int tid = threadIdx.x;
    const int k4  = tid * 4;
    float4 v = *(const float4*)(x + (size_t)row * DDIM + k4);
    float4 w = *(const float4*)(Wb + k4);

    float p = fmaf(v.x, w.x, fmaf(v.y, w.y, fmaf(v.z, w.z, v.w * w.w)));
    #pragma unroll
    for (int off = 16; off > 0; off >>= 1)
        p += __shfl_down_sync(0xffffffffu, p, off);
    __shared__ float red[8];
    if ((tid & 31) == 0) red[tid >> 5] = p;
    __syncthreads();
    if (tid == 0) {
        float s = 0.f;
        #pragma unroll
        for (int i = 0; i < 8; i++) s += red[i];
        g_base[row] = s;
    }

    const int tile = row >> 5, ii = (row >> 4) & 1, rh = (row >> 3) & 1, l4r = row & 7;
    #pragma unroll
    for (int e = 0; e < 4; e++) {
        int k = k4 + e;
        int c = k >> 5, k5 = k & 31;
        int G = (k5 >> 4) & 1, u = (k5 >> 3) & 1, lk = (k5 & 7) >> 1, w_ = k5 & 1;
        g_xh[(size_t)((tile * 32 + c) << 10) + (ii * 2 + G) * 256 +
             (4 * l4r + lk) * 8 + 4 * u + 2 * rh + w_] =
            __float2half_rn(((const float*)&v)[e]);
    }
}

__global__ void __launch_bounds__(NTHREADS, 2)
surv_f16f_kernel(const float* __restrict__ bh,
                 const float* __restrict__ bb,
                 float* __restrict__ out)
{
    __shared__ float seg_s[MTILE * 8];

    const int tid  = threadIdx.x;
    const int nw   = tid >> 5;         // warp = 64-col group (0..7)
    const int lane = tid & 31;
    const int l4   = lane >> 2;
    const int lk   = lane & 3;
    const int row0 = blockIdx.x * MTILE;

    // per-lane stream bases
    const char* agm = (const char*)g_xh + (size_t)blockIdx.x * 65536 + lane * 16;
    const char* bgm = (const char*)g_whs + nw * 4096 + lane * 16;

    float acc[2][8][4];
    #pragma unroll
    for (int i = 0; i < 2; i++)
        #pragma unroll
        for (int j = 0; j < 8; j++)
            #pragma unroll
            for (int q = 0; q < 4; q++) acc[i][j][q] = 0.f;

    // chunk 0 fragments
    uint4 LA00 = *(const uint4*)(agm);
    uint4 LA01 = *(const uint4*)(agm + 512);
    uint4 LA10 = *(const uint4*)(agm + 1024);
    uint4 LA11 = *(const uint4*)(agm + 1536);
    uint4 LB[8];
    #pragma unroll
    for (int j = 0; j < 8; j++)
        LB[j] = *(const uint4*)(bgm + j * 512);

    // ---- mainloop: no smem, no barriers ----
    #pragma unroll 1
    for (int c = 0; c < NCH; c++) {
        const int cn = (c + 1 < NCH) ? (c + 1) : c;   // tail: harmless self-reload
        const char* bnext = bgm + (size_t)cn * 32768;
        const char* anext = agm + (size_t)cn * 2048;

        #pragma unroll
        for (int j = 0; j < 8; j++) {
            uint4 b = LB[j];
            mma_f16(acc[0][j], LA00.x, LA00.y, LA00.z, LA00.w, b.x, b.y);
            mma_f16(acc[1][j], LA10.x, LA10.y, LA10.z, LA10.w, b.x, b.y);
            mma_f16(acc[0][j], LA01.x, LA01.y, LA01.z, LA01.w, b.z, b.w);
            mma_f16(acc[1][j], LA11.x, LA11.y, LA11.z, LA11.w, b.z, b.w);
            LB[j] = *(const uint4*)(bnext + j * 512);   // ~full chunk of slack
        }
        LA00 = *(const uint4*)(anext);
        LA01 = *(const uint4*)(anext + 512);
        LA10 = *(const uint4*)(anext + 1024);
        LA11 = *(const uint4*)(anext + 1536);
    }

    // ---- per-row segmented scan over this warp's 64 cols ----
    float2 bhv[8];
    #pragma unroll
    for (int j = 0; j < 8; j++)
        bhv[j] = __ldg((const float2*)(bh + nw * 64 + 8 * j + 2 * lk));

    #pragma unroll
    for (int i = 0; i < 2; i++) {
        #pragma unroll
        for (int hh = 0; hh < 2; hh++) {
            const int r = 16 * i + 8 * hh + l4;
            float carry = 0.f;
            #pragma unroll
            for (int j = 0; j < 8; j++) {
                float v0 = fmaxf(acc[i][j][2 * hh]     + bhv[j].x, 0.f);
                float v1 = fmaxf(acc[i][j][2 * hh + 1] + bhv[j].y, 0.f);
                float p = v0 + v1;
                float incl = p, t;
                t = __shfl_up_sync(0xffffffffu, incl, 1, 4); if (lk >= 1) incl += t;
                t = __shfl_up_sync(0xffffffffu, incl, 2, 4); if (lk >= 2) incl += t;
                float excl = incl - p;
                acc[i][j][2 * hh]     = carry + excl + v0;
                acc[i][j][2 * hh + 1] = carry + incl;
                carry += __shfl_sync(0xffffffffu, incl, 3, 4);
            }
            if (lk == 0) seg_s[r * 8 + nw] = carry;
        }
    }
    __syncthreads();

    // ---- cross-warp segment prefix + base, store ----
    const float bbv = bb[0];
    #pragma unroll
    for (int i = 0; i < 2; i++) {
        #pragma unroll
        for (int hh = 0; hh < 2; hh++) {
            const int r = 16 * i + 8 * hh + l4;
            float g = __ldg(&g_base[row0 + r]) + bbv;
            #pragma unroll
            for (int s = 0; s < 8; s++)
                if (s < nw) g += seg_s[r * 8 + s];
            float* orow = out + (size_t)(row0 + r) * TDIM + nw * 64 + 2 * lk;
            #pragma unroll
            for (int j = 0; j < 8; j++) {
                float2 o;
                o.x = acc[i][j][2 * hh]     + g;
                o.y = acc[i][j][2 * hh + 1] + g;
                *(float2*)(orow + 8 * j) = o;
            }
        }
    }
}

extern "C" void kernel_launch(void* const* d_in, const int* in_sizes, int n_in,
                              void* d_out, int out_size)
{
    const float* x  = (const float*)d_in[0];
    const float* Wh = (const float*)d_in[1];
    const float* bh = (const float*)d_in[2];
    const float* Wb = (const float*)d_in[3];
    const float* bb = (const float*)d_in[4];
    float* out = (float*)d_out;
    (void)in_sizes; (void)n_in; (void)out_size;

    prep_wh_kernel<<<TDIM, 256>>>(Wh);
    prep_x_kernel<<<BROWS, 256>>>(x, Wb);
    surv_f16f_kernel<<<BROWS / MTILE, NTHREADS>>>(bh, bb, out);
}